// round 3
// baseline (speedup 1.0000x reference)
#include <cuda_runtime.h>
#include <math.h>

#define DM   1024
#define NH   16
#define DK   64
#define SEQ  2048
#define BB   2
#define TOK  (BB*SEQ)   // 4096

// ---------------- scratch (__device__ globals; no allocation allowed) -------
__device__ float g_Qh[BB*NH*SEQ*DK];   // [B,H,S,DK]
__device__ float g_Kh[BB*NH*SEQ*DK];
__device__ float g_Vh[BB*NH*SEQ*DK];
__device__ float g_ctx[TOK*DM];        // [B,S,DM]

// ---------------------------------------------------------------------------
// GEMM: C = A[M,DM] @ W[N,DM]^T + bias   (M=4096 tokens, N=1024)
// 64x64 tile, BK=16, 256 threads, 4x4 per thread.
// Core device routine shared by the fused-QKV and single-GEMM entry points.
// HEADLAYOUT=1: write into [B,H,S,DK] layout; 0: plain [t, n].
// ---------------------------------------------------------------------------
template<int HEADLAYOUT>
__device__ __forceinline__
void gemm_core(const float* __restrict__ A, const float* __restrict__ W,
               const float* __restrict__ bias, float* __restrict__ C)
{
    __shared__ float As[16][68];   // [k][m]
    __shared__ float Bs[16][68];   // [k][n]

    const int tid = threadIdx.x;
    const int tx  = tid & 15;       // n sub
    const int ty  = tid >> 4;       // m sub
    const int m0  = blockIdx.y << 6;
    const int n0  = blockIdx.x << 6;

    const int lm  = tid >> 2;            // 0..63 row within tile
    const int lk4 = (tid & 3) << 2;      // 0,4,8,12

    const float* Ap = A + (size_t)(m0 + lm) * DM + lk4;
    const float* Wp = W + (size_t)(n0 + lm) * DM + lk4;

    float acc[4][4];
    #pragma unroll
    for (int i = 0; i < 4; i++)
        #pragma unroll
        for (int j = 0; j < 4; j++) acc[i][j] = 0.f;

    for (int k0 = 0; k0 < DM; k0 += 16) {
        float4 av = *(const float4*)(Ap + k0);
        float4 wv = *(const float4*)(Wp + k0);
        As[lk4+0][lm] = av.x; As[lk4+1][lm] = av.y;
        As[lk4+2][lm] = av.z; As[lk4+3][lm] = av.w;
        Bs[lk4+0][lm] = wv.x; Bs[lk4+1][lm] = wv.y;
        Bs[lk4+2][lm] = wv.z; Bs[lk4+3][lm] = wv.w;
        __syncthreads();

        #pragma unroll
        for (int kk = 0; kk < 16; kk++) {
            float4 a = *(const float4*)&As[kk][ty << 2];
            float4 b = *(const float4*)&Bs[kk][tx << 2];
            float ar[4] = {a.x, a.y, a.z, a.w};
            float br[4] = {b.x, b.y, b.z, b.w};
            #pragma unroll
            for (int i = 0; i < 4; i++)
                #pragma unroll
                for (int j = 0; j < 4; j++)
                    acc[i][j] = fmaf(ar[i], br[j], acc[i][j]);
        }
        __syncthreads();
    }

    const int n = n0 + (tx << 2);
    float b0 = bias[n+0], b1 = bias[n+1], b2 = bias[n+2], b3 = bias[n+3];
    #pragma unroll
    for (int i = 0; i < 4; i++) {
        int t = m0 + (ty << 2) + i;
        float4 r = make_float4(acc[i][0]+b0, acc[i][1]+b1, acc[i][2]+b2, acc[i][3]+b3);
        if (HEADLAYOUT) {
            int bb = t >> 11;          // t / SEQ
            int s  = t & (SEQ - 1);
            int h  = n >> 6;           // whole tile is one head (n0 multiple of 64)
            int d  = n & 63;
            *(float4*)&C[(size_t)(((bb*NH + h)*SEQ) + s)*DK + d] = r;
        } else {
            *(float4*)&C[(size_t)t * DM + n] = r;
        }
    }
}

// Fused Q/K/V projections: blockIdx.z in {0,1,2} selects which projection.
__global__ __launch_bounds__(256)
void gemm_qkv(const float* __restrict__ q_in, const float* __restrict__ k_in,
              const float* __restrict__ v_in,
              const float* __restrict__ Wq, const float* __restrict__ bq,
              const float* __restrict__ Wk, const float* __restrict__ bk,
              const float* __restrict__ Wv, const float* __restrict__ bv,
              float* __restrict__ Qh, float* __restrict__ Kh,
              float* __restrict__ Vh)
{
    const int z = blockIdx.z;
    const float* A    = (z == 0) ? q_in : (z == 1) ? k_in : v_in;
    const float* W    = (z == 0) ? Wq   : (z == 1) ? Wk   : Wv;
    const float* bias = (z == 0) ? bq   : (z == 1) ? bk   : bv;
    float*       C    = (z == 0) ? Qh   : (z == 1) ? Kh   : Vh;
    gemm_core<1>(A, W, bias, C);
}

// Output projection: ctx[B,S,DM] @ Wo^T + bo -> out
__global__ __launch_bounds__(256)
void gemm_out(const float* __restrict__ A, const float* __restrict__ W,
              const float* __restrict__ bias, float* __restrict__ C)
{
    gemm_core<0>(A, W, bias, C);
}

// ---------------------------------------------------------------------------
// Flash attention: one block = (b, h, 64-query tile). Online softmax over
// 32 key-tiles of 64. 256 threads; 4x4 microtiles for both S=QK^T and O=PV.
// Q pre-scaled by 1/sqrt(DK). Mask is key-only; masked scores -> exactly -1e9.
// ---------------------------------------------------------------------------
__global__ __launch_bounds__(256)
void flash_kernel(const float* __restrict__ Qh, const float* __restrict__ Kh,
                  const float* __restrict__ Vh, const int* __restrict__ mask,
                  float* __restrict__ ctx)
{
    extern __shared__ float sm[];
    float* Qs  = sm;                 // [d][q] stride 68 (transposed)
    float* KVs = sm + 64*68;         // K: [d][k] stride 68 ; V: [k][d] stride 68
    float* Ps  = sm + 2*64*68;       // [k][q] stride 68

    const int tid = threadIdx.x;
    const int tx  = tid & 15;
    const int ty  = tid >> 4;
    const int q0  = blockIdx.x << 6;
    const int h   = blockIdx.y;
    const int b   = blockIdx.z;

    const float* Qg = Qh + (size_t)((b*NH + h)*SEQ + q0) * DK;
    const float* Kg = Kh + (size_t)((b*NH + h)*SEQ) * DK;
    const float* Vg = Vh + (size_t)((b*NH + h)*SEQ) * DK;
    const int*   mb = mask + b * SEQ;

    // load Q tile transposed + pre-scale by 1/sqrt(64)
    {
        const float sc = 0.125f;
        #pragma unroll
        for (int r = 0; r < 4; r++) {
            int q  = (tid >> 4) + r*16;
            int d4 = (tid & 15) << 2;
            float4 v = *(const float4*)(Qg + (size_t)q*DK + d4);
            Qs[(d4+0)*68 + q] = v.x * sc;
            Qs[(d4+1)*68 + q] = v.y * sc;
            Qs[(d4+2)*68 + q] = v.z * sc;
            Qs[(d4+3)*68 + q] = v.w * sc;
        }
    }

    float m_[4], l_[4], O[4][4];
    #pragma unroll
    for (int i = 0; i < 4; i++) {
        m_[i] = -1e30f; l_[i] = 0.f;
        #pragma unroll
        for (int j = 0; j < 4; j++) O[i][j] = 0.f;
    }

    for (int kt = 0; kt < SEQ/64; kt++) {
        const int k0 = kt << 6;
        __syncthreads();                       // prev O-GEMM done with KVs/Ps
        // load K tile transposed: KVs[d][k]
        #pragma unroll
        for (int r = 0; r < 4; r++) {
            int k  = (tid >> 4) + r*16;
            int d4 = (tid & 15) << 2;
            float4 v = *(const float4*)(Kg + (size_t)(k0 + k)*DK + d4);
            KVs[(d4+0)*68 + k] = v.x;
            KVs[(d4+1)*68 + k] = v.y;
            KVs[(d4+2)*68 + k] = v.z;
            KVs[(d4+3)*68 + k] = v.w;
        }
        __syncthreads();

        // scores s[4q][4k]
        float s[4][4];
        #pragma unroll
        for (int i = 0; i < 4; i++)
            #pragma unroll
            for (int j = 0; j < 4; j++) s[i][j] = 0.f;

        #pragma unroll 8
        for (int d = 0; d < 64; d++) {
            float4 qa = *(const float4*)&Qs[d*68 + (ty << 2)];
            float4 kb = *(const float4*)&KVs[d*68 + (tx << 2)];
            float ar[4] = {qa.x, qa.y, qa.z, qa.w};
            float br[4] = {kb.x, kb.y, kb.z, kb.w};
            #pragma unroll
            for (int i = 0; i < 4; i++)
                #pragma unroll
                for (int j = 0; j < 4; j++)
                    s[i][j] = fmaf(ar[i], br[j], s[i][j]);
        }

        // mask (key-only)
        int mk[4];
        #pragma unroll
        for (int j = 0; j < 4; j++) mk[j] = mb[k0 + (tx << 2) + j];
        #pragma unroll
        for (int i = 0; i < 4; i++)
            #pragma unroll
            for (int j = 0; j < 4; j++)
                if (mk[j] == 0) s[i][j] = -1.0e9f;

        // online softmax update per query row
        #pragma unroll
        for (int i = 0; i < 4; i++) {
            float rm = fmaxf(fmaxf(s[i][0], s[i][1]), fmaxf(s[i][2], s[i][3]));
            #pragma unroll
            for (int off = 8; off >= 1; off >>= 1)
                rm = fmaxf(rm, __shfl_xor_sync(0xffffffffu, rm, off));
            float nm   = fmaxf(m_[i], rm);
            float corr = __expf(m_[i] - nm);
            float rs = 0.f;
            #pragma unroll
            for (int j = 0; j < 4; j++) {
                float p = __expf(s[i][j] - nm);
                s[i][j] = p;
                rs += p;
            }
            #pragma unroll
            for (int off = 8; off >= 1; off >>= 1)
                rs += __shfl_xor_sync(0xffffffffu, rs, off);
            l_[i] = l_[i] * corr + rs;
            m_[i] = nm;
            #pragma unroll
            for (int j = 0; j < 4; j++) O[i][j] *= corr;
        }

        // store P transposed: Ps[k][q]
        #pragma unroll
        for (int j = 0; j < 4; j++)
            #pragma unroll
            for (int i = 0; i < 4; i++)
                Ps[((tx << 2) + j)*68 + (ty << 2) + i] = s[i][j];
        __syncthreads();                       // P ready; K reads done

        // load V tile (natural layout): KVs[k][d]
        #pragma unroll
        for (int r = 0; r < 4; r++) {
            int k  = (tid >> 4) + r*16;
            int d4 = (tid & 15) << 2;
            float4 v = *(const float4*)(Vg + (size_t)(k0 + k)*DK + d4);
            *(float4*)&KVs[k*68 + d4] = v;
        }
        __syncthreads();

        // O += P*V GEMM: O[4q][4d] over 64 keys
        #pragma unroll 8
        for (int k = 0; k < 64; k++) {
            float4 pa = *(const float4*)&Ps[k*68 + (ty << 2)];
            float4 vb = *(const float4*)&KVs[k*68 + (tx << 2)];
            float ar[4] = {pa.x, pa.y, pa.z, pa.w};
            float br[4] = {vb.x, vb.y, vb.z, vb.w};
            #pragma unroll
            for (int i = 0; i < 4; i++)
                #pragma unroll
                for (int j = 0; j < 4; j++)
                    O[i][j] = fmaf(ar[i], br[j], O[i][j]);
        }
    }

    // finalize: divide by l, write ctx in [B,S,DM] layout
    #pragma unroll
    for (int i = 0; i < 4; i++) {
        float inv = 1.0f / l_[i];
        int s = q0 + (ty << 2) + i;
        float4 r = make_float4(O[i][0]*inv, O[i][1]*inv, O[i][2]*inv, O[i][3]*inv);
        *(float4*)&ctx[(size_t)(b*SEQ + s)*DM + h*DK + (tx << 2)] = r;
    }
}

// ---------------------------------------------------------------------------
extern "C" void kernel_launch(void* const* d_in, const int* in_sizes, int n_in,
                              void* d_out, int out_size)
{
    (void)in_sizes; (void)n_in; (void)out_size;
    const float* query = (const float*)d_in[0];
    const float* key_  = (const float*)d_in[1];
    const float* value = (const float*)d_in[2];
    const int*   mask  = (const int*)  d_in[3];
    const float* Wq = (const float*)d_in[4];
    const float* bq = (const float*)d_in[5];
    const float* Wk = (const float*)d_in[6];
    const float* bk = (const float*)d_in[7];
    const float* Wv = (const float*)d_in[8];
    const float* bv = (const float*)d_in[9];
    const float* Wo = (const float*)d_in[10];
    const float* bo = (const float*)d_in[11];
    float* out = (float*)d_out;

    float *Qh, *Kh, *Vh, *ctx;
    cudaGetSymbolAddress((void**)&Qh,  g_Qh);
    cudaGetSymbolAddress((void**)&Kh,  g_Kh);
    cudaGetSymbolAddress((void**)&Vh,  g_Vh);
    cudaGetSymbolAddress((void**)&ctx, g_ctx);

    // Fused QKV projections: (16, 64, 3) blocks of 256 threads
    gemm_qkv<<<dim3(DM/64, TOK/64, 3), 256>>>(query, key_, value,
                                              Wq, bq, Wk, bk, Wv, bv,
                                              Qh, Kh, Vh);

    size_t shm = (size_t)3 * 64 * 68 * sizeof(float);   // 52224 B
    cudaFuncSetAttribute(flash_kernel,
                         cudaFuncAttributeMaxDynamicSharedMemorySize, (int)shm);
    flash_kernel<<<dim3(SEQ/64, NH, BB), 256, shm>>>(Qh, Kh, Vh, mask, ctx);

    gemm_out<<<dim3(DM/64, TOK/64), 256>>>(ctx, Wo, bo, out);
}